// round 6
// baseline (speedup 1.0000x reference)
#include <cuda_runtime.h>

#define N_NODES 50000
#define IN_C    256
#define HID     128
#define N_EDGES 800000
#define SCAN_B  256
#define SCAN_NB ((N_NODES + SCAN_B - 1) / SCAN_B)   // 196

// ---- device scratch: referenced ONLY from device code (never passed from host!) ----
__device__ float g_hs[N_NODES * HID];      // (x @ W_conv) * dinv[row]
__device__ int   g_count[N_NODES];
__device__ int   g_rowptr[N_NODES + 1];
__device__ int   g_cursor[N_NODES];
__device__ int   g_col[N_EDGES];
__device__ float g_dinv[N_NODES];
__device__ float g_bias2[IN_C];
__device__ int   g_blocksum[SCAN_NB];

// ---------------- degree histogram ----------------
__global__ void k_count_init() {
    for (int i = blockIdx.x * blockDim.x + threadIdx.x; i < N_NODES;
         i += gridDim.x * blockDim.x)
        g_count[i] = 0;
}

__global__ void k_count(const int* __restrict__ dst) {
    for (int e = blockIdx.x * blockDim.x + threadIdx.x; e < N_EDGES;
         e += gridDim.x * blockDim.x)
        atomicAdd(&g_count[dst[e]], 1);
}

// ---------------- 2-level exclusive scan -> rowptr ----------------
__global__ void k_scan1() {
    __shared__ int sh[SCAN_B];
    int i = blockIdx.x * SCAN_B + threadIdx.x;
    int v = (i < N_NODES) ? g_count[i] : 0;
    sh[threadIdx.x] = v;
    __syncthreads();
    #pragma unroll
    for (int o = 1; o < SCAN_B; o <<= 1) {
        int t = (threadIdx.x >= o) ? sh[threadIdx.x - o] : 0;
        __syncthreads();
        sh[threadIdx.x] += t;
        __syncthreads();
    }
    if (i < N_NODES) g_rowptr[i] = sh[threadIdx.x] - v;
    if (threadIdx.x == SCAN_B - 1) g_blocksum[blockIdx.x] = sh[SCAN_B - 1];
}

__global__ void k_scan2() {
    __shared__ int sh[256];
    int v = (threadIdx.x < SCAN_NB) ? g_blocksum[threadIdx.x] : 0;
    sh[threadIdx.x] = v;
    __syncthreads();
    #pragma unroll
    for (int o = 1; o < 256; o <<= 1) {
        int t = (threadIdx.x >= o) ? sh[threadIdx.x - o] : 0;
        __syncthreads();
        sh[threadIdx.x] += t;
        __syncthreads();
    }
    if (threadIdx.x < SCAN_NB) g_blocksum[threadIdx.x] = sh[threadIdx.x] - v;
}

__global__ void k_scan3() {
    int i = blockIdx.x * SCAN_B + threadIdx.x;
    if (i < N_NODES) {
        int r = g_rowptr[i] + g_blocksum[i / SCAN_B];
        g_rowptr[i] = r;
        g_cursor[i] = r;
        g_dinv[i]   = rsqrtf((float)(g_count[i] + 1));   // +1 self loop
    }
    if (i == 0 && blockIdx.x == 0) g_rowptr[N_NODES] = N_EDGES;
}

// ---------------- CSR fill ----------------
__global__ void k_fill(const int* __restrict__ src, const int* __restrict__ dst) {
    for (int e = blockIdx.x * blockDim.x + threadIdx.x; e < N_EDGES;
         e += gridDim.x * blockDim.x) {
        int p = atomicAdd(&g_cursor[dst[e]], 1);
        g_col[p] = src[e];
    }
}

// ---------------- bias fold: b_conv @ W_lin + b_lin ----------------
__global__ void k_bias2(const float* __restrict__ b_conv,
                        const float* __restrict__ W_lin,
                        const float* __restrict__ b_lin) {
    int j = blockIdx.x * blockDim.x + threadIdx.x;
    if (j < IN_C) {
        float s = b_lin[j];
        #pragma unroll 4
        for (int k = 0; k < HID; k++) s += b_conv[k] * W_lin[k * IN_C + j];
        g_bias2[j] = s;
    }
}

// ---------------- GEMM1: g_hs = (x @ W_conv) * dinv[row] ----------------
// Only genuine harness pointers as params; g_hs/g_dinv via device symbols.
__global__ void gemm1_kernel(const float* __restrict__ A,   // x [N,256]
                             const float* __restrict__ B) { // W_conv [256,128]
    constexpr int K = IN_C, N = HID;
    constexpr int BM = 64, BN = 64, BK = 16, TM = 4, TN = 4;
    __shared__ float As[BK][BM];
    __shared__ float Bs[BK][BN];

    const int tid = threadIdx.x;                 // 256 threads
    const int tx  = tid % (BN / TN);
    const int ty  = tid / (BN / TN);
    const int rowBase = blockIdx.y * BM;
    const int colBase = blockIdx.x * BN;

    float acc[TM][TN] = {};

    for (int k0 = 0; k0 < K; k0 += BK) {
        {
            int idx = tid * 4;
            int r = idx / BK;
            int c = idx % BK;
            int grow = rowBase + r;
            float4 v = make_float4(0.f, 0.f, 0.f, 0.f);
            if (grow < N_NODES)
                v = *reinterpret_cast<const float4*>(&A[(size_t)grow * K + k0 + c]);
            As[c + 0][r] = v.x;
            As[c + 1][r] = v.y;
            As[c + 2][r] = v.z;
            As[c + 3][r] = v.w;
        }
        {
            int idx = tid * 4;
            int r = idx / BN;
            int c = idx % BN;
            float4 v = *reinterpret_cast<const float4*>(&B[(size_t)(k0 + r) * N + colBase + c]);
            *reinterpret_cast<float4*>(&Bs[r][c]) = v;
        }
        __syncthreads();

        #pragma unroll
        for (int k = 0; k < BK; k++) {
            float a[TM], b[TN];
            #pragma unroll
            for (int i = 0; i < TM; i++) a[i] = As[k][ty * TM + i];
            #pragma unroll
            for (int j = 0; j < TN; j++) b[j] = Bs[k][tx * TN + j];
            #pragma unroll
            for (int i = 0; i < TM; i++)
                #pragma unroll
                for (int j = 0; j < TN; j++)
                    acc[i][j] += a[i] * b[j];
        }
        __syncthreads();
    }

    #pragma unroll
    for (int i = 0; i < TM; i++) {
        int grow = rowBase + ty * TM + i;
        if (grow >= N_NODES) continue;
        float dv = g_dinv[grow];
        float4 v;
        v.x = acc[i][0] * dv;
        v.y = acc[i][1] * dv;
        v.z = acc[i][2] * dv;
        v.w = acc[i][3] * dv;
        *reinterpret_cast<float4*>(&g_hs[(size_t)grow * HID + colBase + tx * TN]) = v;
    }
}

// ---------------- FUSED gather + GEMM2 ----------------
// Per block: 64 nodes. Phase 1: agg[n] = dinv[n]*(hs[n] + sum_{j in in(n)} hs[j]) -> smem.
// Phase 2: out[64,256] = agg[64,128] @ W_lin[128,256] + bias2.
__global__ __launch_bounds__(256, 2)
void k_fused(const float* __restrict__ W_lin,
             float* __restrict__ out) {
    __shared__ float sAgg[64][HID];    // 32 KB
    __shared__ float sB[8][IN_C];      // 8 KB

    const int tid = threadIdx.x;       // 256
    const int w   = tid >> 5;          // warp 0..7
    const int l   = tid & 31;          // lane
    const int rowBase = blockIdx.x * 64;

    // ---- Phase 1: gather ----
    const float4* hs4 = reinterpret_cast<const float4*>(g_hs);
    #pragma unroll
    for (int q = 0; q < 8; q++) {
        int nLocal = w * 8 + q;
        int i = rowBase + nLocal;
        float4 acc = make_float4(0.f, 0.f, 0.f, 0.f);
        if (i < N_NODES) {
            acc = hs4[(size_t)i * (HID / 4) + l];            // self (dinv[i] folded)
            int beg = g_rowptr[i];
            int end = g_rowptr[i + 1];
            for (int e = beg; e < end; e++) {
                int j = g_col[e];                            // uniform per warp
                float4 v = hs4[(size_t)j * (HID / 4) + l];
                acc.x += v.x; acc.y += v.y; acc.z += v.z; acc.w += v.w;
            }
            float dv = g_dinv[i];
            acc.x *= dv; acc.y *= dv; acc.z *= dv; acc.w *= dv;
        }
        *reinterpret_cast<float4*>(&sAgg[nLocal][l * 4]) = acc;
    }
    __syncthreads();

    // ---- Phase 2: out[64,256] = sAgg[64,128] @ W_lin[128,256] + bias ----
    const int tx = tid & 31;           // cols tx*8 .. tx*8+7
    const int ty = tid >> 5;           // rows ty*8 .. ty*8+7

    float acc[8][8];
    {
        float bj[8];
        #pragma unroll
        for (int j = 0; j < 8; j++) bj[j] = g_bias2[tx * 8 + j];
        #pragma unroll
        for (int i = 0; i < 8; i++)
            #pragma unroll
            for (int j = 0; j < 8; j++) acc[i][j] = bj[j];
    }

    for (int k0 = 0; k0 < HID; k0 += 8) {
        #pragma unroll
        for (int q = 0; q < 2; q++) {
            int lin = (q * 256 + tid) * 4;     // 0..2044 step 4
            int r = lin >> 8;
            int c = lin & 255;
            *reinterpret_cast<float4*>(&sB[r][c]) =
                *reinterpret_cast<const float4*>(&W_lin[(size_t)(k0 + r) * IN_C + c]);
        }
        __syncthreads();

        #pragma unroll
        for (int k = 0; k < 8; k++) {
            float a[8];
            #pragma unroll
            for (int i = 0; i < 8; i++) a[i] = sAgg[ty * 8 + i][k0 + k];
            float4 b0 = *reinterpret_cast<const float4*>(&sB[k][tx * 8]);
            float4 b1 = *reinterpret_cast<const float4*>(&sB[k][tx * 8 + 4]);
            float b[8] = {b0.x, b0.y, b0.z, b0.w, b1.x, b1.y, b1.z, b1.w};
            #pragma unroll
            for (int i = 0; i < 8; i++)
                #pragma unroll
                for (int j = 0; j < 8; j++)
                    acc[i][j] += a[i] * b[j];
        }
        __syncthreads();
    }

    float4* out4 = reinterpret_cast<float4*>(out);
    #pragma unroll
    for (int i = 0; i < 8; i++) {
        int grow = rowBase + ty * 8 + i;
        if (grow >= N_NODES) continue;
        float4 v0 = make_float4(acc[i][0], acc[i][1], acc[i][2], acc[i][3]);
        float4 v1 = make_float4(acc[i][4], acc[i][5], acc[i][6], acc[i][7]);
        out4[(size_t)grow * (IN_C / 4) + tx * 2 + 0] = v0;
        out4[(size_t)grow * (IN_C / 4) + tx * 2 + 1] = v1;
    }
}

// ---------------- launch ----------------
extern "C" void kernel_launch(void* const* d_in, const int* in_sizes, int n_in,
                              void* d_out, int out_size) {
    const float* x      = nullptr;
    const int*   eidx   = nullptr;
    const float* W_conv = nullptr;
    const float* W_lin  = nullptr;
    const float* b_conv = nullptr;
    const float* b_lin  = nullptr;

    for (int i = 0; i < n_in; i++) {
        int sz = in_sizes[i];
        const void* p = d_in[i];
        if      (sz == N_NODES * IN_C) x = (const float*)p;
        else if (sz == 2 * N_EDGES)    eidx = (const int*)p;
        else if (sz == IN_C * HID) { if (!W_conv) W_conv = (const float*)p;
                                     else         W_lin  = (const float*)p; }
        else if (sz == HID)            b_conv = (const float*)p;
        else if (sz == IN_C)           b_lin  = (const float*)p;
    }
    if (!x || !eidx || !W_conv || !W_lin || !b_conv || !b_lin) {
        x      = (const float*)d_in[0];
        eidx   = (const int*)d_in[1];
        W_conv = (const float*)d_in[2];
        b_conv = (const float*)d_in[3];
        W_lin  = (const float*)d_in[4];
        b_lin  = (const float*)d_in[5];
    }

    float* out = (float*)d_out;          // [N, 256]
    const int* src = eidx;               // edge_index[0]
    const int* dst = eidx + N_EDGES;     // edge_index[1]

    // CSR build + normalization
    k_count_init<<<196, 256>>>();
    k_count<<<3125, 256>>>(dst);
    k_scan1<<<SCAN_NB, SCAN_B>>>();
    k_scan2<<<1, 256>>>();
    k_scan3<<<SCAN_NB, SCAN_B>>>();
    k_fill<<<3125, 256>>>(src, dst);

    // bias fold
    k_bias2<<<2, 128>>>(b_conv, W_lin, b_lin);

    // GEMM1: g_hs = (x @ W_conv) * dinv[row]
    {
        dim3 grid(HID / 64, (N_NODES + 63) / 64);   // (2, 782)
        gemm1_kernel<<<grid, 256>>>(x, W_conv);
    }

    // FUSED gather + GEMM2 -> out
    k_fused<<<(N_NODES + 63) / 64, 256>>>(W_lin, out);
}